// round 13
// baseline (speedup 1.0000x reference)
#include <cuda_runtime.h>
#include <cuda_fp16.h>
#include <cstdint>

// DCNv2 forward on GB300: fp16 mma.sync m16n8k16, fp16 x, ldmatrix B-frags.
// Main GEMM: N-tile 128 (2 h-rows), 512 threads, 128 CTAs.
// B=4, Cin=Cout=256, H=W=64, DG=2, K=3x3. KTOT=2304, NCOL=16384.

#define BATCH 4
#define CIN   256
#define COUT  256
#define Hdim  64
#define Wdim  64
#define HW    4096
#define KTOT  2304
#define NCOL  16384
#define NCHUNK 72                 // K chunks of 32

// ---------------- device scratch (no cudaMalloc) ----------------------------
__device__ __half   g_xth[BATCH * HW * CIN];  // x transposed fp16 [b][pos][c] 8MB
__device__ uint32_t g_wrf[NCHUNK * 4096];     // main A fp16 frag-packed
__device__ uint32_t g_wofff[NCHUNK * 1024];   // offset A fp16 frag-packed
__device__ float    g_om2[54 * NCOL];         // offset conv out [ch][pos]
__device__ float4   g_pw[BATCH * 2 * 9 * HW]; // bilinear weights (mask premul)
__device__ int4     g_pi[BATCH * 2 * 9 * HW]; // bilinear corner offsets

// ---------------- helpers ---------------------------------------------------
__device__ __forceinline__ void mma_fp16(float* d, const uint32_t* a, const uint32_t* b) {
    asm volatile(
        "mma.sync.aligned.m16n8k16.row.col.f32.f16.f16.f32 "
        "{%0,%1,%2,%3}, {%4,%5,%6,%7}, {%8,%9}, {%0,%1,%2,%3};"
        : "+f"(d[0]), "+f"(d[1]), "+f"(d[2]), "+f"(d[3])
        : "r"(a[0]), "r"(a[1]), "r"(a[2]), "r"(a[3]), "r"(b[0]), "r"(b[1]));
}
__device__ __forceinline__ uint32_t pack_h2(float f0, float f1) {
    __half2 h = __floats2half2_rn(f0, f1);
    return *(const uint32_t*)&h;
}
#define LDSM_X4(r0, r1, r2, r3, a) \
    asm volatile("ldmatrix.sync.aligned.m8n8.x4.shared.b16 {%0,%1,%2,%3}, [%4];" \
                 : "=r"(r0), "=r"(r1), "=r"(r2), "=r"(r3) : "r"(a))
#define CP_ASYNC16(sa, gp) \
    asm volatile("cp.async.cg.shared.global [%0], [%1], 16;" :: "r"(sa), "l"(gp))
#define CP_COMMIT() asm volatile("cp.async.commit_group;" ::: "memory")
#define CP_WAIT0()  asm volatile("cp.async.wait_group 0;" ::: "memory")

// ---------------- K0: fragment-pack weights (fp16, m16n8k16 layout) ---------
__global__ void k_repack(const float* __restrict__ weight,
                         const float* __restrict__ w_off) {
    int i = blockIdx.x * blockDim.x + threadIdx.x;
    if (i < NCHUNK * 4096) {
        int c = i >> 12, r2 = i & 4095;
        int s = r2 >> 11, mt = (r2 >> 7) & 15, lane = (r2 >> 2) & 31, r = r2 & 3;
        int row = mt * 16 + (lane >> 2) + 8 * (r & 1);
        int kk = c * 32 + s * 16 + (lane & 3) * 2 + 8 * (r >> 1);
        float f0, f1;
        {
            int dg = kk / 1152, km = (kk >> 7) % 9, cc = kk & 127;
            f0 = weight[(row * CIN + dg * 128 + cc) * 9 + km];
        }
        {
            int kk1 = kk + 1;
            int dg = kk1 / 1152, km = (kk1 >> 7) % 9, cc = kk1 & 127;
            f1 = weight[(row * CIN + dg * 128 + cc) * 9 + km];
        }
        g_wrf[i] = pack_h2(f0, f1);
    }
    if (i < NCHUNK * 1024) {
        int c = i >> 10, r2 = i & 1023;
        int s = r2 >> 9, mt = (r2 >> 7) & 3, lane = (r2 >> 2) & 31, r = r2 & 3;
        int row = mt * 16 + (lane >> 2) + 8 * (r & 1);
        int kk = c * 32 + s * 16 + (lane & 3) * 2 + 8 * (r >> 1);
        float f0 = 0.f, f1 = 0.f;
        if (row < 54) {
            int k9 = kk >> 8, cc = kk & 255;
            f0 = w_off[(row * CIN + cc) * 9 + k9];
            int kk1 = kk + 1, k91 = kk1 >> 8, cc1 = kk1 & 255;
            f1 = w_off[(row * CIN + cc1) * 9 + k91];
        }
        g_wofff[i] = pack_h2(f0, f1);
    }
}

// ---------------- K1: transpose x -> fp16 [b][pos][c] -----------------------
__global__ void k_transpose(const float* __restrict__ x) {
    __shared__ float t[32][33];
    int b = blockIdx.z;
    int p0 = blockIdx.x * 32, c0 = blockIdx.y * 32;
    int tx = threadIdx.x, ty = threadIdx.y;
#pragma unroll
    for (int j = 0; j < 32; j += 8)
        t[ty + j][tx] = x[((size_t)b * CIN + c0 + ty + j) * HW + p0 + tx];
    __syncthreads();
#pragma unroll
    for (int j = 0; j < 32; j += 8)
        g_xth[((size_t)b * HW + p0 + ty + j) * CIN + c0 + tx] = __float2half(t[tx][ty + j]);
}

// ---------------- K2: offset-conv GEMM (fp16), latency-hidden ---------------
__global__ __launch_bounds__(256, 2) void k_offgemm(const float* __restrict__ b_off) {
    __shared__ uint32_t As[2][1024];
    __shared__ __align__(16) __half Bs[2][2048];
    const int tid = threadIdx.x, lane = tid & 31, wid = tid >> 5;
    const int b = blockIdx.x >> 6, h = blockIdx.x & 63;
    const int warp_m = wid & 1, warp_n = wid >> 1;
    const int wq = tid >> 2, q = tid & 3;

    float acc[2][2][4];
#pragma unroll
    for (int i = 0; i < 2; i++)
#pragma unroll
        for (int t = 0; t < 2; t++)
#pragma unroll
            for (int r = 0; r < 4; r++) acc[i][t][r] = 0.f;

    uint32_t as_sm[2];
    as_sm[0] = (uint32_t)__cvta_generic_to_shared(&As[0][0]);
    as_sm[1] = (uint32_t)__cvta_generic_to_shared(&As[1][0]);

    uint4 rv;
    auto gatherB = [&](int cc) {
        int k9 = cc >> 3, cb = (cc & 7) * 32;
        int gy = h + k9 / 3 - 1, gx = wq + k9 % 3 - 1;
        rv = make_uint4(0, 0, 0, 0);
        if (gy >= 0 && gy < Hdim && gx >= 0 && gx < Wdim)
            rv = *(const uint4*)(g_xth + ((size_t)(b * HW + gy * 64 + gx)) * 256 + cb + q * 8);
    };
    auto storeB = [&](int dst) {
        *(uint4*)&Bs[dst][((q >> 1) * 64 + wq) * 16 + (q & 1) * 8] = rv;
    };
    auto loadA = [&](int cc, int dst) {
        const uint4* src = (const uint4*)(g_wofff + cc * 1024);
        CP_ASYNC16(as_sm[dst] + tid * 16, src + tid);
        CP_COMMIT();
    };

    gatherB(0); storeB(0); loadA(0, 0);

    for (int c = 0; c < NCHUNK; c++) {
        const int buf = c & 1;
        CP_WAIT0();
        __syncthreads();
        if (c + 1 < NCHUNK) {
            gatherB(c + 1);
            loadA(c + 1, buf ^ 1);
        }
#pragma unroll
        for (int s = 0; s < 2; s++) {
            uint32_t af[2][4], bf[2][2];
#pragma unroll
            for (int i = 0; i < 2; i++) {
                const uint4* p = (const uint4*)&As[buf][((s * 4 + warp_m * 2 + i) * 32 + lane) * 4];
                uint4 v = *p;
                af[i][0] = v.x; af[i][1] = v.y; af[i][2] = v.z; af[i][3] = v.w;
            }
#pragma unroll
            for (int t = 0; t < 2; t++) {
                int col = (warp_n * 2 + t) * 8 + (lane >> 2);
                const __half* base = &Bs[buf][(s * 64 + col) * 16 + (lane & 3) * 2];
                bf[t][0] = *(const uint32_t*)base;
                bf[t][1] = *(const uint32_t*)(base + 8);
            }
#pragma unroll
            for (int i = 0; i < 2; i++)
#pragma unroll
                for (int t = 0; t < 2; t++)
                    mma_fp16(acc[i][t], af[i], bf[t]);
        }
        if (c + 1 < NCHUNK) storeB(buf ^ 1);
    }
#pragma unroll
    for (int i = 0; i < 2; i++) {
        int ch0 = (warp_m * 2 + i) * 16 + (lane >> 2);
#pragma unroll
        for (int t = 0; t < 2; t++) {
            int wcol = (warp_n * 2 + t) * 8 + (lane & 3) * 2;
            int pos = b * HW + h * 64 + wcol;
            if (ch0 < 54) {
                float bv = b_off[ch0];
                *(float2*)&g_om2[(size_t)ch0 * NCOL + pos] =
                    make_float2(acc[i][t][0] + bv, acc[i][t][1] + bv);
            }
            if (ch0 + 8 < 54) {
                float bv = b_off[ch0 + 8];
                *(float2*)&g_om2[(size_t)(ch0 + 8) * NCOL + pos] =
                    make_float2(acc[i][t][2] + bv, acc[i][t][3] + bv);
            }
        }
    }
}

// ---------------- K3: offsets -> bilinear params ----------------------------
__global__ void k_params() {
    int i = blockIdx.x * blockDim.x + threadIdx.x;
    int sp = i & 4095;
    int t = i >> 12;
    int k = t % 9; t /= 9;
    int dg = t & 1, b = t >> 1;
    int h = sp >> 6, w = sp & 63;
    int pos = b * HW + sp;

    float oy = g_om2[(size_t)(dg * 18 + k) * NCOL + pos];
    float ox = g_om2[(size_t)(dg * 18 + 9 + k) * NCOL + pos];
    float mr = g_om2[(size_t)(36 + dg * 9 + k) * NCOL + pos];
    float m = 1.f / (1.f + expf(-mr));

    float py = oy + (float)(h + k / 3 - 1);
    float px = ox + (float)(w + k % 3 - 1);
    float y0f = floorf(py), x0f = floorf(px);
    float wy1 = py - y0f, wx1 = px - x0f;
    float wy0 = 1.f - wy1, wx0 = 1.f - wx1;
    int y0 = (int)y0f, x0 = (int)x0f;
    int y1 = y0 + 1, x1 = x0 + 1;
    float fy0 = (y0 >= 0 && y0 < Hdim) ? 1.f : 0.f;
    float fy1 = (y1 >= 0 && y1 < Hdim) ? 1.f : 0.f;
    float fx0 = (x0 >= 0 && x0 < Wdim) ? 1.f : 0.f;
    float fx1 = (x1 >= 0 && x1 < Wdim) ? 1.f : 0.f;
    int iy0 = min(max(y0, 0), Hdim - 1) * Wdim;
    int iy1 = min(max(y1, 0), Hdim - 1) * Wdim;
    int ix0 = min(max(x0, 0), Wdim - 1);
    int ix1 = min(max(x1, 0), Wdim - 1);

    g_pw[i] = make_float4(wy0 * wx0 * m * fy0 * fx0, wy0 * wx1 * m * fy0 * fx1,
                          wy1 * wx0 * m * fy1 * fx0, wy1 * wx1 * m * fy1 * fx1);
    g_pi[i] = make_int4(iy0 + ix0, iy0 + ix1, iy1 + ix0, iy1 + ix1);
}

// ---------------- K4: main GEMM (fp16, M=256 x N=128), sampling fused -------
// 512 threads, 128 CTAs (2 h-rows each).
// B smem: halves[(s*128+col)*24 + khalf*8 + j] (48B stride, conflict-free).
// smem bytes: As 2x16384 | Bs 2x12288 | pw 36864 | pi 18432 = 112640
#define SMB_AS  0
#define SMB_BS  32768
#define BS_BUF  12288
#define SMB_PW  57344
#define SMB_PI  94208
#define SMB_TOT 112640
__global__ __launch_bounds__(512, 1) void k_maingemm(const float* __restrict__ bias,
                                                     float* __restrict__ outp) {
    extern __shared__ __align__(16) char dsm[];
    uint32_t* AsU[2] = { (uint32_t*)(dsm + SMB_AS), (uint32_t*)(dsm + SMB_AS + 16384) };
    __half*   BsH[2] = { (__half*)(dsm + SMB_BS), (__half*)(dsm + SMB_BS + BS_BUF) };
    float4*  pwS = (float4*)(dsm + SMB_PW);
    ushort4* piS = (ushort4*)(dsm + SMB_PI);
    const int tid = threadIdx.x, lane = tid & 31, wid = tid >> 5;
    const int b = blockIdx.x >> 5;               // 32 col-tiles per batch
    const int hw0 = (blockIdx.x & 31) * 128;     // 2 h-rows
    const int warp_m = wid & 3, warp_n = wid >> 2;   // 4m x 4n warp grid
    const int wq = tid >> 2, q = tid & 3;        // wq = column 0..127

    // preload params: 18 taps x 128 positions
    for (int i = tid; i < 2304; i += 512) {
        int t = i >> 7, posw = i & 127;          // t = dg*9+km
        int dg = t / 9, km = t % 9;
        int gidx = ((b * 2 + dg) * 9 + km) * HW + hw0 + posw;
        pwS[i] = g_pw[gidx];
        int4 p = g_pi[gidx];
        piS[i] = make_ushort4((unsigned short)p.x, (unsigned short)p.y,
                              (unsigned short)p.z, (unsigned short)p.w);
    }

    float acc[4][4][4];
#pragma unroll
    for (int i = 0; i < 4; i++)
#pragma unroll
        for (int t = 0; t < 4; t++)
#pragma unroll
            for (int r = 0; r < 4; r++) acc[i][t][r] = 0.f;

    uint32_t as_sm[2];
    as_sm[0] = (uint32_t)__cvta_generic_to_shared(AsU[0]);
    as_sm[1] = (uint32_t)__cvta_generic_to_shared(AsU[1]);

    // ldmatrix lane addresses
    uint32_t lmaddr[2][2];
    {
        int seg = lane >> 3, row = lane & 7;
        int tsel = seg >> 1, khalf = seg & 1;
        uint32_t bs0 = (uint32_t)__cvta_generic_to_shared(BsH[0]);
#pragma unroll
        for (int s = 0; s < 2; s++)
#pragma unroll
            for (int p = 0; p < 2; p++) {
                int col = (warp_n * 4 + p * 2 + tsel) * 8 + row;
                lmaddr[s][p] = bs0 + ((s * 128 + col) * 24 + khalf * 8) * 2;
            }
    }

    auto loadA = [&](int cc, int dst) {
        const uint4* src = (const uint4*)(g_wrf + (size_t)cc * 4096);
        CP_ASYNC16(as_sm[dst] + tid * 16, src + tid);
        CP_ASYNC16(as_sm[dst] + (tid + 512) * 16, src + tid + 512);
        CP_COMMIT();
    };

    uint4 ga, gb, gc, gd; float4 rpw;
    auto gatherB = [&](int cc) {
        int grp = cc >> 2, cb = (cc & 3) * 32;
        int dg = grp / 9;
        int pidx = grp * 128 + wq;
        rpw = pwS[pidx];
        ushort4 pi = piS[pidx];
        const __half* xb = g_xth + ((size_t)b * HW) * 256 + dg * 128 + cb + q * 8;
        ga = *(const uint4*)(xb + (size_t)pi.x * 256);
        gb = *(const uint4*)(xb + (size_t)pi.y * 256);
        gc = *(const uint4*)(xb + (size_t)pi.z * 256);
        gd = *(const uint4*)(xb + (size_t)pi.w * 256);
    };
    auto storeB = [&](int dst) {
        const __half2* ha = (const __half2*)&ga;
        const __half2* hb = (const __half2*)&gb;
        const __half2* hc = (const __half2*)&gc;
        const __half2* hd = (const __half2*)&gd;
        uint32_t o[4];
#pragma unroll
        for (int j = 0; j < 4; j++) {
            float2 a = __half22float2(ha[j]);
            float2 bb = __half22float2(hb[j]);
            float2 cc2 = __half22float2(hc[j]);
            float2 dd = __half22float2(hd[j]);
            float vx = rpw.x * a.x + rpw.y * bb.x + rpw.z * cc2.x + rpw.w * dd.x;
            float vy = rpw.x * a.y + rpw.y * bb.y + rpw.z * cc2.y + rpw.w * dd.y;
            o[j] = pack_h2(vx, vy);
        }
        *(uint4*)&BsH[dst][((q >> 1) * 128 + wq) * 24 + (q & 1) * 8] =
            make_uint4(o[0], o[1], o[2], o[3]);
    };

    __syncthreads();                       // param table ready
    gatherB(0); storeB(0); loadA(0, 0);

    for (int c = 0; c < NCHUNK; c++) {
        const int buf = c & 1;
        const uint32_t boff = buf * BS_BUF;
        CP_WAIT0();
        __syncthreads();
        if (c + 1 < NCHUNK) {
            gatherB(c + 1);
            loadA(c + 1, buf ^ 1);
        }
#pragma unroll
        for (int s = 0; s < 2; s++) {
            uint32_t af[4][4], bf[4][2];
#pragma unroll
            for (int i = 0; i < 4; i++) {
                const uint4* p = (const uint4*)&AsU[buf][((s * 16 + warp_m * 4 + i) * 32 + lane) * 4];
                uint4 v = *p;
                af[i][0] = v.x; af[i][1] = v.y; af[i][2] = v.z; af[i][3] = v.w;
            }
#pragma unroll
            for (int p = 0; p < 2; p++) {
                uint32_t r0, r1, r2, r3;
                LDSM_X4(r0, r1, r2, r3, lmaddr[s][p] + boff);
                bf[p * 2][0] = r0; bf[p * 2][1] = r1;
                bf[p * 2 + 1][0] = r2; bf[p * 2 + 1][1] = r3;
            }
#pragma unroll
            for (int i = 0; i < 4; i++)
#pragma unroll
                for (int t = 0; t < 4; t++)
                    mma_fp16(acc[i][t], af[i], bf[t]);
        }
        if (c + 1 < NCHUNK) storeB(buf ^ 1);
    }
    // epilogue -> out[b][oc][h][w] (+bias)
#pragma unroll
    for (int i = 0; i < 4; i++) {
        int oc0 = (warp_m * 4 + i) * 16 + (lane >> 2);
        float bv0 = bias[oc0], bv8 = bias[oc0 + 8];
#pragma unroll
        for (int t = 0; t < 4; t++) {
            int wcol = (warp_n * 4 + t) * 8 + (lane & 3) * 2;
            size_t base = ((size_t)(b * 256 + oc0)) * HW + hw0 + wcol;
            *(float2*)&outp[base] = make_float2(acc[i][t][0] + bv0, acc[i][t][1] + bv0);
            *(float2*)&outp[base + 8 * HW] = make_float2(acc[i][t][2] + bv8, acc[i][t][3] + bv8);
        }
    }
}

// ---------------- launch ----------------------------------------------------
extern "C" void kernel_launch(void* const* d_in, const int* in_sizes, int n_in,
                              void* d_out, int out_size) {
    const float* x      = (const float*)d_in[0];
    const float* w_off  = (const float*)d_in[1];
    const float* b_off  = (const float*)d_in[2];
    const float* weight = (const float*)d_in[3];
    const float* bias   = (const float*)d_in[4];
    float* out = (float*)d_out;

    cudaFuncSetAttribute(k_maingemm, cudaFuncAttributeMaxDynamicSharedMemorySize, SMB_TOT);

    k_repack<<<(NCHUNK * 4096 + 255) / 256, 256>>>(weight, w_off);
    k_transpose<<<dim3(HW / 32, CIN / 32, BATCH), dim3(32, 8)>>>(x);
    k_offgemm<<<256, 256>>>(b_off);
    k_params<<<BATCH * 2 * 9 * HW / 256, 256>>>();
    k_maingemm<<<128, 512, SMB_TOT>>>(bias, out);
}

// round 14
// speedup vs baseline: 1.1209x; 1.1209x over previous
#include <cuda_runtime.h>
#include <cuda_fp16.h>
#include <cstdint>

// DCNv2 forward on GB300: fp16 mma.sync m16n8k16, fp16 x, ldmatrix B-frags.
// Main GEMM: 256 CTAs x 256 thr (M=256, N=64), K-chunk 64, split-gather pipeline.
// B=4, Cin=Cout=256, H=W=64, DG=2, K=3x3. KTOT=2304, NCOL=16384.

#define BATCH 4
#define CIN   256
#define COUT  256
#define Hdim  64
#define Wdim  64
#define HW    4096
#define KTOT  2304
#define NCOL  16384
#define NCHUNK 72                 // K chunks of 32 (repack granularity)
#define NCH64  36                 // K chunks of 64 (main GEMM)

// ---------------- device scratch (no cudaMalloc) ----------------------------
__device__ __half   g_xth[BATCH * HW * CIN];  // x transposed fp16 [b][pos][c] 8MB
__device__ uint32_t g_wrf[NCHUNK * 4096];     // main A fp16 frag-packed
__device__ uint32_t g_wofff[NCHUNK * 1024];   // offset A fp16 frag-packed
__device__ float    g_om2[54 * NCOL];         // offset conv out [ch][pos]
__device__ float4   g_pw[BATCH * 2 * 9 * HW]; // bilinear weights (mask premul)
__device__ ushort4  g_pi16[BATCH * 2 * 9 * HW]; // bilinear corner offsets packed

// ---------------- helpers ---------------------------------------------------
__device__ __forceinline__ void mma_fp16(float* d, const uint32_t* a, const uint32_t* b) {
    asm volatile(
        "mma.sync.aligned.m16n8k16.row.col.f32.f16.f16.f32 "
        "{%0,%1,%2,%3}, {%4,%5,%6,%7}, {%8,%9}, {%0,%1,%2,%3};"
        : "+f"(d[0]), "+f"(d[1]), "+f"(d[2]), "+f"(d[3])
        : "r"(a[0]), "r"(a[1]), "r"(a[2]), "r"(a[3]), "r"(b[0]), "r"(b[1]));
}
__device__ __forceinline__ uint32_t pack_h2(float f0, float f1) {
    __half2 h = __floats2half2_rn(f0, f1);
    return *(const uint32_t*)&h;
}
#define LDSM_X4(r0, r1, r2, r3, a) \
    asm volatile("ldmatrix.sync.aligned.m8n8.x4.shared.b16 {%0,%1,%2,%3}, [%4];" \
                 : "=r"(r0), "=r"(r1), "=r"(r2), "=r"(r3) : "r"(a))
#define CP_ASYNC16(sa, gp) \
    asm volatile("cp.async.cg.shared.global [%0], [%1], 16;" :: "r"(sa), "l"(gp))
#define CP_COMMIT() asm volatile("cp.async.commit_group;" ::: "memory")
#define CP_WAIT0()  asm volatile("cp.async.wait_group 0;" ::: "memory")

// ---------------- K0: fragment-pack weights (fp16, m16n8k16 layout) ---------
__global__ void k_repack(const float* __restrict__ weight,
                         const float* __restrict__ w_off) {
    int i = blockIdx.x * blockDim.x + threadIdx.x;
    if (i < NCHUNK * 4096) {
        int c = i >> 12, r2 = i & 4095;
        int s = r2 >> 11, mt = (r2 >> 7) & 15, lane = (r2 >> 2) & 31, r = r2 & 3;
        int row = mt * 16 + (lane >> 2) + 8 * (r & 1);
        int kk = c * 32 + s * 16 + (lane & 3) * 2 + 8 * (r >> 1);
        float f0, f1;
        {
            int dg = kk / 1152, km = (kk >> 7) % 9, cc = kk & 127;
            f0 = weight[(row * CIN + dg * 128 + cc) * 9 + km];
        }
        {
            int kk1 = kk + 1;
            int dg = kk1 / 1152, km = (kk1 >> 7) % 9, cc = kk1 & 127;
            f1 = weight[(row * CIN + dg * 128 + cc) * 9 + km];
        }
        g_wrf[i] = pack_h2(f0, f1);
    }
    if (i < NCHUNK * 1024) {
        int c = i >> 10, r2 = i & 1023;
        int s = r2 >> 9, mt = (r2 >> 7) & 3, lane = (r2 >> 2) & 31, r = r2 & 3;
        int row = mt * 16 + (lane >> 2) + 8 * (r & 1);
        int kk = c * 32 + s * 16 + (lane & 3) * 2 + 8 * (r >> 1);
        float f0 = 0.f, f1 = 0.f;
        if (row < 54) {
            int k9 = kk >> 8, cc = kk & 255;
            f0 = w_off[(row * CIN + cc) * 9 + k9];
            int kk1 = kk + 1, k91 = kk1 >> 8, cc1 = kk1 & 255;
            f1 = w_off[(row * CIN + cc1) * 9 + k91];
        }
        g_wofff[i] = pack_h2(f0, f1);
    }
}

// ---------------- K1: transpose x -> fp16 [b][pos][c] -----------------------
__global__ void k_transpose(const float* __restrict__ x) {
    __shared__ float t[32][33];
    int b = blockIdx.z;
    int p0 = blockIdx.x * 32, c0 = blockIdx.y * 32;
    int tx = threadIdx.x, ty = threadIdx.y;
#pragma unroll
    for (int j = 0; j < 32; j += 8)
        t[ty + j][tx] = x[((size_t)b * CIN + c0 + ty + j) * HW + p0 + tx];
    __syncthreads();
#pragma unroll
    for (int j = 0; j < 32; j += 8)
        g_xth[((size_t)b * HW + p0 + ty + j) * CIN + c0 + tx] = __float2half(t[tx][ty + j]);
}

// ---------------- K2: offset-conv GEMM (fp16), latency-hidden ---------------
__global__ __launch_bounds__(256, 2) void k_offgemm(const float* __restrict__ b_off) {
    __shared__ uint32_t As[2][1024];
    __shared__ __align__(16) __half Bs[2][2048];
    const int tid = threadIdx.x, lane = tid & 31, wid = tid >> 5;
    const int b = blockIdx.x >> 6, h = blockIdx.x & 63;
    const int warp_m = wid & 1, warp_n = wid >> 1;
    const int wq = tid >> 2, q = tid & 3;

    float acc[2][2][4];
#pragma unroll
    for (int i = 0; i < 2; i++)
#pragma unroll
        for (int t = 0; t < 2; t++)
#pragma unroll
            for (int r = 0; r < 4; r++) acc[i][t][r] = 0.f;

    uint32_t as_sm[2];
    as_sm[0] = (uint32_t)__cvta_generic_to_shared(&As[0][0]);
    as_sm[1] = (uint32_t)__cvta_generic_to_shared(&As[1][0]);

    uint4 rv;
    auto gatherB = [&](int cc) {
        int k9 = cc >> 3, cb = (cc & 7) * 32;
        int gy = h + k9 / 3 - 1, gx = wq + k9 % 3 - 1;
        rv = make_uint4(0, 0, 0, 0);
        if (gy >= 0 && gy < Hdim && gx >= 0 && gx < Wdim)
            rv = *(const uint4*)(g_xth + ((size_t)(b * HW + gy * 64 + gx)) * 256 + cb + q * 8);
    };
    auto storeB = [&](int dst) {
        *(uint4*)&Bs[dst][((q >> 1) * 64 + wq) * 16 + (q & 1) * 8] = rv;
    };
    auto loadA = [&](int cc, int dst) {
        const uint4* src = (const uint4*)(g_wofff + cc * 1024);
        CP_ASYNC16(as_sm[dst] + tid * 16, src + tid);
        CP_COMMIT();
    };

    gatherB(0); storeB(0); loadA(0, 0);

    for (int c = 0; c < NCHUNK; c++) {
        const int buf = c & 1;
        CP_WAIT0();
        __syncthreads();
        if (c + 1 < NCHUNK) {
            gatherB(c + 1);
            loadA(c + 1, buf ^ 1);
        }
#pragma unroll
        for (int s = 0; s < 2; s++) {
            uint32_t af[2][4], bf[2][2];
#pragma unroll
            for (int i = 0; i < 2; i++) {
                const uint4* p = (const uint4*)&As[buf][((s * 4 + warp_m * 2 + i) * 32 + lane) * 4];
                uint4 v = *p;
                af[i][0] = v.x; af[i][1] = v.y; af[i][2] = v.z; af[i][3] = v.w;
            }
#pragma unroll
            for (int t = 0; t < 2; t++) {
                int col = (warp_n * 2 + t) * 8 + (lane >> 2);
                const __half* base = &Bs[buf][(s * 64 + col) * 16 + (lane & 3) * 2];
                bf[t][0] = *(const uint32_t*)base;
                bf[t][1] = *(const uint32_t*)(base + 8);
            }
#pragma unroll
            for (int i = 0; i < 2; i++)
#pragma unroll
                for (int t = 0; t < 2; t++)
                    mma_fp16(acc[i][t], af[i], bf[t]);
        }
        if (c + 1 < NCHUNK) storeB(buf ^ 1);
    }
#pragma unroll
    for (int i = 0; i < 2; i++) {
        int ch0 = (warp_m * 2 + i) * 16 + (lane >> 2);
#pragma unroll
        for (int t = 0; t < 2; t++) {
            int wcol = (warp_n * 2 + t) * 8 + (lane & 3) * 2;
            int pos = b * HW + h * 64 + wcol;
            if (ch0 < 54) {
                float bv = b_off[ch0];
                *(float2*)&g_om2[(size_t)ch0 * NCOL + pos] =
                    make_float2(acc[i][t][0] + bv, acc[i][t][1] + bv);
            }
            if (ch0 + 8 < 54) {
                float bv = b_off[ch0 + 8];
                *(float2*)&g_om2[(size_t)(ch0 + 8) * NCOL + pos] =
                    make_float2(acc[i][t][2] + bv, acc[i][t][3] + bv);
            }
        }
    }
}

// ---------------- K3: offsets -> bilinear params ----------------------------
__global__ void k_params() {
    int i = blockIdx.x * blockDim.x + threadIdx.x;
    int sp = i & 4095;
    int t = i >> 12;
    int k = t % 9; t /= 9;
    int dg = t & 1, b = t >> 1;
    int h = sp >> 6, w = sp & 63;
    int pos = b * HW + sp;

    float oy = g_om2[(size_t)(dg * 18 + k) * NCOL + pos];
    float ox = g_om2[(size_t)(dg * 18 + 9 + k) * NCOL + pos];
    float mr = g_om2[(size_t)(36 + dg * 9 + k) * NCOL + pos];
    float m = 1.f / (1.f + expf(-mr));

    float py = oy + (float)(h + k / 3 - 1);
    float px = ox + (float)(w + k % 3 - 1);
    float y0f = floorf(py), x0f = floorf(px);
    float wy1 = py - y0f, wx1 = px - x0f;
    float wy0 = 1.f - wy1, wx0 = 1.f - wx1;
    int y0 = (int)y0f, x0 = (int)x0f;
    int y1 = y0 + 1, x1 = x0 + 1;
    float fy0 = (y0 >= 0 && y0 < Hdim) ? 1.f : 0.f;
    float fy1 = (y1 >= 0 && y1 < Hdim) ? 1.f : 0.f;
    float fx0 = (x0 >= 0 && x0 < Wdim) ? 1.f : 0.f;
    float fx1 = (x1 >= 0 && x1 < Wdim) ? 1.f : 0.f;
    int iy0 = min(max(y0, 0), Hdim - 1) * Wdim;
    int iy1 = min(max(y1, 0), Hdim - 1) * Wdim;
    int ix0 = min(max(x0, 0), Wdim - 1);
    int ix1 = min(max(x1, 0), Wdim - 1);

    g_pw[i] = make_float4(wy0 * wx0 * m * fy0 * fx0, wy0 * wx1 * m * fy0 * fx1,
                          wy1 * wx0 * m * fy1 * fx0, wy1 * wx1 * m * fy1 * fx1);
    g_pi16[i] = make_ushort4((unsigned short)(iy0 + ix0), (unsigned short)(iy0 + ix1),
                             (unsigned short)(iy1 + ix0), (unsigned short)(iy1 + ix1));
}

// ---------------- K4: main GEMM (fp16, M=256 x N=64, Kc=64) -----------------
// 256 CTAs x 256 threads, occ 2. Split-gather: sub0 before MMA s=0-1,
// combined after; sub32 gathered mid-chunk, combined after s=2-3.
// Params (pw/pi) from global, issued with sub0 gather, consumed at combine.
// B smem: halves[(s*64+col)*24 + khalf*8 + j], s=0..3 -> 12288B/buffer.
// smem: As 2x32768 + Bs 2x12288 = 90112 bytes.
#define SMB_AS  0
#define SMB_BS  65536
#define BS_BUF  12288
#define SMB_TOT 90112
__global__ __launch_bounds__(256, 2) void k_maingemm(const float* __restrict__ bias,
                                                     float* __restrict__ outp) {
    extern __shared__ __align__(16) char dsm[];
    uint32_t* AsU[2] = { (uint32_t*)(dsm + SMB_AS), (uint32_t*)(dsm + SMB_AS + 32768) };
    __half*   BsH[2] = { (__half*)(dsm + SMB_BS), (__half*)(dsm + SMB_BS + BS_BUF) };
    const int tid = threadIdx.x, lane = tid & 31, wid = tid >> 5;
    const int b = blockIdx.x >> 6, h = blockIdx.x & 63;
    const int warp_m = wid & 3, warp_n = wid >> 2;
    const int wq = tid >> 2, q = tid & 3;

    float acc[4][4][4];
#pragma unroll
    for (int i = 0; i < 4; i++)
#pragma unroll
        for (int t = 0; t < 4; t++)
#pragma unroll
            for (int r = 0; r < 4; r++) acc[i][t][r] = 0.f;

    uint32_t as_sm[2];
    as_sm[0] = (uint32_t)__cvta_generic_to_shared(AsU[0]);
    as_sm[1] = (uint32_t)__cvta_generic_to_shared(AsU[1]);

    // ldmatrix lane addresses: 4 k-steps x 2 tile-pairs
    uint32_t lmaddr[4][2];
    {
        int seg = lane >> 3, row = lane & 7;
        int tsel = seg >> 1, khalf = seg & 1;
        uint32_t bs0 = (uint32_t)__cvta_generic_to_shared(BsH[0]);
#pragma unroll
        for (int s = 0; s < 4; s++)
#pragma unroll
            for (int p = 0; p < 2; p++) {
                int col = (warp_n * 4 + p * 2 + tsel) * 8 + row;
                lmaddr[s][p] = bs0 + ((s * 64 + col) * 24 + khalf * 8) * 2;
            }
    }

    auto loadA = [&](int cc, int dst) {   // 32KB = 2048 uint4
        const uint4* src = (const uint4*)(g_wrf + (size_t)cc * 8192);
#pragma unroll
        for (int i = 0; i < 8; i++)
            CP_ASYNC16(as_sm[dst] + (tid + i * 256) * 16, src + tid + i * 256);
        CP_COMMIT();
    };

    uint4 ga, gb, gc, gd; float4 rpw; ushort4 rpi;
    // sub: 0 -> klocal q*8 (s=q>>1), 1 -> klocal 32+q*8 (s=2+(q>>1))
    auto gatherB = [&](int cc, int sub) {
        int grp = cc >> 1;                       // tap: dg*9+km
        int dg = grp / 9;
        if (sub == 0) {
            int gidx = (b * 18 + grp) * HW + h * 64 + wq;
            rpw = g_pw[gidx];
            rpi = g_pi16[gidx];
        }
        int cb = dg * 128 + (cc & 1) * 64 + sub * 32 + q * 8;
        const __half* xb = g_xth + ((size_t)b * HW) * 256 + cb;
        ga = *(const uint4*)(xb + (size_t)rpi.x * 256);
        gb = *(const uint4*)(xb + (size_t)rpi.y * 256);
        gc = *(const uint4*)(xb + (size_t)rpi.z * 256);
        gd = *(const uint4*)(xb + (size_t)rpi.w * 256);
    };
    auto storeB = [&](int dst, int sub) {
        const __half2* ha = (const __half2*)&ga;
        const __half2* hb = (const __half2*)&gb;
        const __half2* hc = (const __half2*)&gc;
        const __half2* hd = (const __half2*)&gd;
        uint32_t o[4];
#pragma unroll
        for (int j = 0; j < 4; j++) {
            float2 a = __half22float2(ha[j]);
            float2 bb = __half22float2(hb[j]);
            float2 cc2 = __half22float2(hc[j]);
            float2 dd = __half22float2(hd[j]);
            float vx = rpw.x * a.x + rpw.y * bb.x + rpw.z * cc2.x + rpw.w * dd.x;
            float vy = rpw.x * a.y + rpw.y * bb.y + rpw.z * cc2.y + rpw.w * dd.y;
            o[j] = pack_h2(vx, vy);
        }
        int s = (q >> 1) + sub * 2;
        *(uint4*)&BsH[dst][(s * 64 + wq) * 24 + (q & 1) * 8] =
            make_uint4(o[0], o[1], o[2], o[3]);
    };

    // prologue: fill Bs[0] fully + A chunk 0
    gatherB(0, 0); storeB(0, 0);
    gatherB(0, 1); storeB(0, 1);
    loadA(0, 0);

    for (int c = 0; c < NCH64; c++) {
        const int buf = c & 1;
        const uint32_t boff = buf * BS_BUF;
        CP_WAIT0();
        __syncthreads();
        const bool nxt = (c + 1 < NCH64);
        if (nxt) {
            gatherB(c + 1, 0);           // LDGs + params, consumed after s=1
            loadA(c + 1, buf ^ 1);
        }
#pragma unroll
        for (int s = 0; s < 2; s++) {
            uint32_t af[4][4], bf[4][2];
#pragma unroll
            for (int i = 0; i < 4; i++) {
                const uint4* p = (const uint4*)&AsU[buf][(s >> 1) * 4096 +
                    (((s & 1) * 16 + warp_m * 4 + i) * 32 + lane) * 4];
                uint4 v = *p;
                af[i][0] = v.x; af[i][1] = v.y; af[i][2] = v.z; af[i][3] = v.w;
            }
#pragma unroll
            for (int p = 0; p < 2; p++) {
                uint32_t r0, r1, r2, r3;
                LDSM_X4(r0, r1, r2, r3, lmaddr[s][p] + boff);
                bf[p * 2][0] = r0; bf[p * 2][1] = r1;
                bf[p * 2 + 1][0] = r2; bf[p * 2 + 1][1] = r3;
            }
#pragma unroll
            for (int i = 0; i < 4; i++)
#pragma unroll
                for (int t = 0; t < 4; t++)
                    mma_fp16(acc[i][t], af[i], bf[t]);
        }
        if (nxt) {
            storeB(buf ^ 1, 0);          // combine sub0 (data arrived)
            gatherB(c + 1, 1);           // issue sub32 LDGs
        }
#pragma unroll
        for (int s = 2; s < 4; s++) {
            uint32_t af[4][4], bf[4][2];
#pragma unroll
            for (int i = 0; i < 4; i++) {
                const uint4* p = (const uint4*)&AsU[buf][(s >> 1) * 4096 +
                    (((s & 1) * 16 + warp_m * 4 + i) * 32 + lane) * 4];
                uint4 v = *p;
                af[i][0] = v.x; af[i][1] = v.y; af[i][2] = v.z; af[i][3] = v.w;
            }
#pragma unroll
            for (int p = 0; p < 2; p++) {
                uint32_t r0, r1, r2, r3;
                LDSM_X4(r0, r1, r2, r3, lmaddr[s][p] + boff);
                bf[p * 2][0] = r0; bf[p * 2][1] = r1;
                bf[p * 2 + 1][0] = r2; bf[p * 2 + 1][1] = r3;
            }
#pragma unroll
            for (int i = 0; i < 4; i++)
#pragma unroll
                for (int t = 0; t < 4; t++)
                    mma_fp16(acc[i][t], af[i], bf[t]);
        }
        if (nxt) storeB(buf ^ 1, 1);     // combine sub32
    }
    // epilogue -> out[b][oc][h][w] (+bias)
#pragma unroll
    for (int i = 0; i < 4; i++) {
        int oc0 = (warp_m * 4 + i) * 16 + (lane >> 2);
        float bv0 = bias[oc0], bv8 = bias[oc0 + 8];
#pragma unroll
        for (int t = 0; t < 4; t++) {
            int wcol = (warp_n * 4 + t) * 8 + (lane & 3) * 2;
            size_t base = ((size_t)(b * 256 + oc0)) * HW + h * 64 + wcol;
            *(float2*)&outp[base] = make_float2(acc[i][t][0] + bv0, acc[i][t][1] + bv0);
            *(float2*)&outp[base + 8 * HW] = make_float2(acc[i][t][2] + bv8, acc[i][t][3] + bv8);
        }
    }
}

// ---------------- launch ----------------------------------------------------
extern "C" void kernel_launch(void* const* d_in, const int* in_sizes, int n_in,
                              void* d_out, int out_size) {
    const float* x      = (const float*)d_in[0];
    const float* w_off  = (const float*)d_in[1];
    const float* b_off  = (const float*)d_in[2];
    const float* weight = (const float*)d_in[3];
    const float* bias   = (const float*)d_in[4];
    float* out = (float*)d_out;

    cudaFuncSetAttribute(k_maingemm, cudaFuncAttributeMaxDynamicSharedMemorySize, SMB_TOT);

    k_repack<<<(NCHUNK * 4096 + 255) / 256, 256>>>(weight, w_off);
    k_transpose<<<dim3(HW / 32, CIN / 32, BATCH), dim3(32, 8)>>>(x);
    k_offgemm<<<256, 256>>>(b_off);
    k_params<<<BATCH * 2 * 9 * HW / 256, 256>>>();
    k_maingemm<<<256, 256, SMB_TOT>>>(bias, out);
}

// round 17
// speedup vs baseline: 1.1337x; 1.0114x over previous
#include <cuda_runtime.h>
#include <cuda_fp16.h>
#include <cstdint>

// DCNv2 forward on GB300: fp16 mma.sync m16n8k16, fused offconv+params,
// merged prep. Main GEMM: 256 CTAs x 256 thr, K-chunk 64, split-gather.
// B=4, Cin=Cout=256, H=W=64, DG=2, K=3x3. KTOT=2304, NCOL=16384.

#define BATCH 4
#define CIN   256
#define COUT  256
#define Hdim  64
#define Wdim  64
#define HW    4096
#define KTOT  2304
#define NCOL  16384
#define NCHUNK 72                 // K chunks of 32 (repack granularity)
#define NCH64  36                 // K chunks of 64 (main GEMM)

// ---------------- device scratch (no cudaMalloc) ----------------------------
__device__ __half   g_xth[BATCH * HW * CIN];  // x transposed fp16 [b][pos][c] 8MB
__device__ uint32_t g_wrf[NCHUNK * 4096];     // main A fp16 frag-packed
__device__ uint32_t g_wofff[NCHUNK * 1024];   // offset A fp16 frag-packed
__device__ float4   g_pw[BATCH * 2 * 9 * HW]; // bilinear weights (mask premul)
__device__ ushort4  g_pi16[BATCH * 2 * 9 * HW]; // bilinear corner offsets packed

// ---------------- helpers ---------------------------------------------------
__device__ __forceinline__ void mma_fp16(float* d, const uint32_t* a, const uint32_t* b) {
    asm volatile(
        "mma.sync.aligned.m16n8k16.row.col.f32.f16.f16.f32 "
        "{%0,%1,%2,%3}, {%4,%5,%6,%7}, {%8,%9}, {%0,%1,%2,%3};"
        : "+f"(d[0]), "+f"(d[1]), "+f"(d[2]), "+f"(d[3])
        : "r"(a[0]), "r"(a[1]), "r"(a[2]), "r"(a[3]), "r"(b[0]), "r"(b[1]));
}
__device__ __forceinline__ uint32_t pack_h2(float f0, float f1) {
    __half2 h = __floats2half2_rn(f0, f1);
    return *(const uint32_t*)&h;
}
#define LDSM_X4(r0, r1, r2, r3, a) \
    asm volatile("ldmatrix.sync.aligned.m8n8.x4.shared.b16 {%0,%1,%2,%3}, [%4];" \
                 : "=r"(r0), "=r"(r1), "=r"(r2), "=r"(r3) : "r"(a))
#define CP_ASYNC16(sa, gp) \
    asm volatile("cp.async.cg.shared.global [%0], [%1], 16;" :: "r"(sa), "l"(gp))
#define CP_COMMIT() asm volatile("cp.async.commit_group;" ::: "memory")
#define CP_WAIT0()  asm volatile("cp.async.wait_group 0;" ::: "memory")

// ---------------- K0: merged prep (repack weights + transpose x) -------------
// blocks [0,1152): fragment repack; blocks [1152, 1152+4096): x transpose.
__global__ __launch_bounds__(256) void k_prep(const float* __restrict__ weight,
                                              const float* __restrict__ w_off,
                                              const float* __restrict__ x) {
    const int tid = threadIdx.x;
    if (blockIdx.x < 1152) {
        int i = blockIdx.x * 256 + tid;
        if (i < NCHUNK * 4096) {
            int c = i >> 12, r2 = i & 4095;
            int s = r2 >> 11, mt = (r2 >> 7) & 15, lane = (r2 >> 2) & 31, r = r2 & 3;
            int row = mt * 16 + (lane >> 2) + 8 * (r & 1);
            int kk = c * 32 + s * 16 + (lane & 3) * 2 + 8 * (r >> 1);
            float f0, f1;
            {
                int dg = kk / 1152, km = (kk >> 7) % 9, cc = kk & 127;
                f0 = weight[(row * CIN + dg * 128 + cc) * 9 + km];
            }
            {
                int kk1 = kk + 1;
                int dg = kk1 / 1152, km = (kk1 >> 7) % 9, cc = kk1 & 127;
                f1 = weight[(row * CIN + dg * 128 + cc) * 9 + km];
            }
            g_wrf[i] = pack_h2(f0, f1);
        }
        if (i < NCHUNK * 1024) {
            int c = i >> 10, r2 = i & 1023;
            int s = r2 >> 9, mt = (r2 >> 7) & 3, lane = (r2 >> 2) & 31, r = r2 & 3;
            int row = mt * 16 + (lane >> 2) + 8 * (r & 1);
            int kk = c * 32 + s * 16 + (lane & 3) * 2 + 8 * (r >> 1);
            float f0 = 0.f, f1 = 0.f;
            if (row < 54) {
                int k9 = kk >> 8, cc = kk & 255;
                f0 = w_off[(row * CIN + cc) * 9 + k9];
                int kk1 = kk + 1, k91 = kk1 >> 8, cc1 = kk1 & 255;
                f1 = w_off[(row * CIN + cc1) * 9 + k91];
            }
            g_wofff[i] = pack_h2(f0, f1);
        }
    } else {
        __shared__ float t[32][33];
        int bid = blockIdx.x - 1152;
        int b = bid >> 10;
        int p0 = (bid & 127) * 32, c0 = ((bid >> 7) & 7) * 32;
        int tx = tid & 31, ty = tid >> 5;
#pragma unroll
        for (int j = 0; j < 32; j += 8)
            t[ty + j][tx] = x[((size_t)b * CIN + c0 + ty + j) * HW + p0 + tx];
        __syncthreads();
#pragma unroll
        for (int j = 0; j < 32; j += 8)
            g_xth[((size_t)b * HW + p0 + ty + j) * CIN + c0 + tx] =
                __float2half(t[tx][ty + j]);
    }
}

// ---------------- K1: offset-conv GEMM + fused params -----------------------
__global__ __launch_bounds__(256, 2) void k_offgemm(const float* __restrict__ b_off) {
    __shared__ uint32_t As[2][1024];
    __shared__ __align__(16) __half Bs[2][2048];
    __shared__ float omS[54 * 64];       // 13.8KB: CTA's om tile [ch][w]
    const int tid = threadIdx.x, lane = tid & 31, wid = tid >> 5;
    const int b = blockIdx.x >> 6, h = blockIdx.x & 63;
    const int warp_m = wid & 1, warp_n = wid >> 1;
    const int wq = tid >> 2, q = tid & 3;

    float acc[2][2][4];
#pragma unroll
    for (int i = 0; i < 2; i++)
#pragma unroll
        for (int t = 0; t < 2; t++)
#pragma unroll
            for (int r = 0; r < 4; r++) acc[i][t][r] = 0.f;

    uint32_t as_sm[2];
    as_sm[0] = (uint32_t)__cvta_generic_to_shared(&As[0][0]);
    as_sm[1] = (uint32_t)__cvta_generic_to_shared(&As[1][0]);

    uint4 rv;
    auto gatherB = [&](int cc) {
        int k9 = cc >> 3, cb = (cc & 7) * 32;
        int gy = h + k9 / 3 - 1, gx = wq + k9 % 3 - 1;
        rv = make_uint4(0, 0, 0, 0);
        if (gy >= 0 && gy < Hdim && gx >= 0 && gx < Wdim)
            rv = *(const uint4*)(g_xth + ((size_t)(b * HW + gy * 64 + gx)) * 256 + cb + q * 8);
    };
    auto storeB = [&](int dst) {
        *(uint4*)&Bs[dst][((q >> 1) * 64 + wq) * 16 + (q & 1) * 8] = rv;
    };
    auto loadA = [&](int cc, int dst) {
        const uint4* src = (const uint4*)(g_wofff + cc * 1024);
        CP_ASYNC16(as_sm[dst] + tid * 16, src + tid);
        CP_COMMIT();
    };

    gatherB(0); storeB(0); loadA(0, 0);

    for (int c = 0; c < NCHUNK; c++) {
        const int buf = c & 1;
        CP_WAIT0();
        __syncthreads();
        if (c + 1 < NCHUNK) {
            gatherB(c + 1);
            loadA(c + 1, buf ^ 1);
        }
#pragma unroll
        for (int s = 0; s < 2; s++) {
            uint32_t af[2][4], bf[2][2];
#pragma unroll
            for (int i = 0; i < 2; i++) {
                const uint4* p = (const uint4*)&As[buf][((s * 4 + warp_m * 2 + i) * 32 + lane) * 4];
                uint4 v = *p;
                af[i][0] = v.x; af[i][1] = v.y; af[i][2] = v.z; af[i][3] = v.w;
            }
#pragma unroll
            for (int t = 0; t < 2; t++) {
                int col = (warp_n * 2 + t) * 8 + (lane >> 2);
                const __half* base = &Bs[buf][(s * 64 + col) * 16 + (lane & 3) * 2];
                bf[t][0] = *(const uint32_t*)base;
                bf[t][1] = *(const uint32_t*)(base + 8);
            }
#pragma unroll
            for (int i = 0; i < 2; i++)
#pragma unroll
                for (int t = 0; t < 2; t++)
                    mma_fp16(acc[i][t], af[i], bf[t]);
        }
        if (c + 1 < NCHUNK) storeB(buf ^ 1);
    }
    // epilogue: om tile -> smem (+b_off)
#pragma unroll
    for (int i = 0; i < 2; i++) {
        int ch0 = (warp_m * 2 + i) * 16 + (lane >> 2);
#pragma unroll
        for (int t = 0; t < 2; t++) {
            int wcol = (warp_n * 2 + t) * 8 + (lane & 3) * 2;
            if (ch0 < 54) {
                float bv = b_off[ch0];
                omS[ch0 * 64 + wcol]     = acc[i][t][0] + bv;
                omS[ch0 * 64 + wcol + 1] = acc[i][t][1] + bv;
            }
            if (ch0 + 8 < 54) {
                float bv = b_off[ch0 + 8];
                omS[(ch0 + 8) * 64 + wcol]     = acc[i][t][2] + bv;
                omS[(ch0 + 8) * 64 + wcol + 1] = acc[i][t][3] + bv;
            }
        }
    }
    __syncthreads();
    // fused params: 18 taps x 64 positions
    for (int i = tid; i < 1152; i += 256) {
        int t = i >> 6, w = i & 63;              // t = dg*9+k
        int dg = t / 9, k = t % 9;
        float oy = omS[(dg * 18 + k) * 64 + w];
        float ox = omS[(dg * 18 + 9 + k) * 64 + w];
        float mr = omS[(36 + dg * 9 + k) * 64 + w];
        float m = 1.f / (1.f + expf(-mr));

        float py = oy + (float)(h + k / 3 - 1);
        float px = ox + (float)(w + k % 3 - 1);
        float y0f = floorf(py), x0f = floorf(px);
        float wy1 = py - y0f, wx1 = px - x0f;
        float wy0 = 1.f - wy1, wx0 = 1.f - wx1;
        int y0 = (int)y0f, x0 = (int)x0f;
        int y1 = y0 + 1, x1 = x0 + 1;
        float fy0 = (y0 >= 0 && y0 < Hdim) ? 1.f : 0.f;
        float fy1 = (y1 >= 0 && y1 < Hdim) ? 1.f : 0.f;
        float fx0 = (x0 >= 0 && x0 < Wdim) ? 1.f : 0.f;
        float fx1 = (x1 >= 0 && x1 < Wdim) ? 1.f : 0.f;
        int iy0 = min(max(y0, 0), Hdim - 1) * Wdim;
        int iy1 = min(max(y1, 0), Hdim - 1) * Wdim;
        int ix0 = min(max(x0, 0), Wdim - 1);
        int ix1 = min(max(x1, 0), Wdim - 1);

        int gidx = (b * 18 + t) * HW + h * 64 + w;
        g_pw[gidx] = make_float4(wy0 * wx0 * m * fy0 * fx0, wy0 * wx1 * m * fy0 * fx1,
                                 wy1 * wx0 * m * fy1 * fx0, wy1 * wx1 * m * fy1 * fx1);
        g_pi16[gidx] = make_ushort4((unsigned short)(iy0 + ix0), (unsigned short)(iy0 + ix1),
                                    (unsigned short)(iy1 + ix0), (unsigned short)(iy1 + ix1));
    }
}

// ---------------- K2: main GEMM (fp16, M=256 x N=64, Kc=64) -----------------
// 256 CTAs x 256 threads, occ 2. Split-gather pipeline; params from global,
// issued with sub0 gather, consumed at combine (~32 HMMA later).
// B smem: halves[(s*64+col)*24 + khalf*8 + j], s=0..3 -> 12288B/buffer.
#define SMB_AS  0
#define SMB_BS  65536
#define BS_BUF  12288
#define SMB_TOT 90112
__global__ __launch_bounds__(256, 2) void k_maingemm(const float* __restrict__ bias,
                                                     float* __restrict__ outp) {
    extern __shared__ __align__(16) char dsm[];
    uint32_t* AsU[2] = { (uint32_t*)(dsm + SMB_AS), (uint32_t*)(dsm + SMB_AS + 32768) };
    __half*   BsH[2] = { (__half*)(dsm + SMB_BS), (__half*)(dsm + SMB_BS + BS_BUF) };
    const int tid = threadIdx.x, lane = tid & 31, wid = tid >> 5;
    const int b = blockIdx.x >> 6, h = blockIdx.x & 63;
    const int warp_m = wid & 3, warp_n = wid >> 2;
    const int wq = tid >> 2, q = tid & 3;

    float acc[4][4][4];
#pragma unroll
    for (int i = 0; i < 4; i++)
#pragma unroll
        for (int t = 0; t < 4; t++)
#pragma unroll
            for (int r = 0; r < 4; r++) acc[i][t][r] = 0.f;

    uint32_t as_sm[2];
    as_sm[0] = (uint32_t)__cvta_generic_to_shared(AsU[0]);
    as_sm[1] = (uint32_t)__cvta_generic_to_shared(AsU[1]);

    uint32_t lmaddr[4][2];
    {
        int seg = lane >> 3, row = lane & 7;
        int tsel = seg >> 1, khalf = seg & 1;
        uint32_t bs0 = (uint32_t)__cvta_generic_to_shared(BsH[0]);
#pragma unroll
        for (int s = 0; s < 4; s++)
#pragma unroll
            for (int p = 0; p < 2; p++) {
                int col = (warp_n * 4 + p * 2 + tsel) * 8 + row;
                lmaddr[s][p] = bs0 + ((s * 64 + col) * 24 + khalf * 8) * 2;
            }
    }

    auto loadA = [&](int cc, int dst) {   // 32KB = 2048 uint4
        const uint4* src = (const uint4*)(g_wrf + (size_t)cc * 8192);
#pragma unroll
        for (int i = 0; i < 8; i++)
            CP_ASYNC16(as_sm[dst] + (tid + i * 256) * 16, src + tid + i * 256);
        CP_COMMIT();
    };

    uint4 ga, gb, gc, gd; float4 rpw; ushort4 rpi;
    auto gatherB = [&](int cc, int sub) {
        int grp = cc >> 1;                       // tap: dg*9+km
        int dg = grp / 9;
        if (sub == 0) {
            int gidx = (b * 18 + grp) * HW + h * 64 + wq;
            rpw = g_pw[gidx];
            rpi = g_pi16[gidx];
        }
        int cb = dg * 128 + (cc & 1) * 64 + sub * 32 + q * 8;
        const __half* xb = g_xth + ((size_t)b * HW) * 256 + cb;
        ga = *(const uint4*)(xb + (size_t)rpi.x * 256);
        gb = *(const uint4*)(xb + (size_t)rpi.y * 256);
        gc = *(const uint4*)(xb + (size_t)rpi.z * 256);
        gd = *(const uint4*)(xb + (size_t)rpi.w * 256);
    };
    auto storeB = [&](int dst, int sub) {
        const __half2* ha = (const __half2*)&ga;
        const __half2* hb = (const __half2*)&gb;
        const __half2* hc = (const __half2*)&gc;
        const __half2* hd = (const __half2*)&gd;
        uint32_t o[4];
#pragma unroll
        for (int j = 0; j < 4; j++) {
            float2 a = __half22float2(ha[j]);
            float2 bb = __half22float2(hb[j]);
            float2 cc2 = __half22float2(hc[j]);
            float2 dd = __half22float2(hd[j]);
            float vx = rpw.x * a.x + rpw.y * bb.x + rpw.z * cc2.x + rpw.w * dd.x;
            float vy = rpw.x * a.y + rpw.y * bb.y + rpw.z * cc2.y + rpw.w * dd.y;
            o[j] = pack_h2(vx, vy);
        }
        int s = (q >> 1) + sub * 2;
        *(uint4*)&BsH[dst][(s * 64 + wq) * 24 + (q & 1) * 8] =
            make_uint4(o[0], o[1], o[2], o[3]);
    };

    gatherB(0, 0); storeB(0, 0);
    gatherB(0, 1); storeB(0, 1);
    loadA(0, 0);

    for (int c = 0; c < NCH64; c++) {
        const int buf = c & 1;
        const uint32_t boff = buf * BS_BUF;
        CP_WAIT0();
        __syncthreads();
        const bool nxt = (c + 1 < NCH64);
        if (nxt) {
            gatherB(c + 1, 0);
            loadA(c + 1, buf ^ 1);
        }
#pragma unroll
        for (int s = 0; s < 2; s++) {
            uint32_t af[4][4], bf[4][2];
#pragma unroll
            for (int i = 0; i < 4; i++) {
                const uint4* p = (const uint4*)&AsU[buf][(s >> 1) * 4096 +
                    (((s & 1) * 16 + warp_m * 4 + i) * 32 + lane) * 4];
                uint4 v = *p;
                af[i][0] = v.x; af[i][1] = v.y; af[i][2] = v.z; af[i][3] = v.w;
            }
#pragma unroll
            for (int p = 0; p < 2; p++) {
                uint32_t r0, r1, r2, r3;
                LDSM_X4(r0, r1, r2, r3, lmaddr[s][p] + boff);
                bf[p * 2][0] = r0; bf[p * 2][1] = r1;
                bf[p * 2 + 1][0] = r2; bf[p * 2 + 1][1] = r3;
            }
#pragma unroll
            for (int i = 0; i < 4; i++)
#pragma unroll
                for (int t = 0; t < 4; t++)
                    mma_fp16(acc[i][t], af[i], bf[t]);
        }
        if (nxt) {
            storeB(buf ^ 1, 0);
            gatherB(c + 1, 1);
        }
#pragma unroll
        for (int s = 2; s < 4; s++) {
            uint32_t af[4][4], bf[4][2];
#pragma unroll
            for (int i = 0; i < 4; i++) {
                const uint4* p = (const uint4*)&AsU[buf][(s >> 1) * 4096 +
                    (((s & 1) * 16 + warp_m * 4 + i) * 32 + lane) * 4];
                uint4 v = *p;
                af[i][0] = v.x; af[i][1] = v.y; af[i][2] = v.z; af[i][3] = v.w;
            }
#pragma unroll
            for (int p = 0; p < 2; p++) {
                uint32_t r0, r1, r2, r3;
                LDSM_X4(r0, r1, r2, r3, lmaddr[s][p] + boff);
                bf[p * 2][0] = r0; bf[p * 2][1] = r1;
                bf[p * 2 + 1][0] = r2; bf[p * 2 + 1][1] = r3;
            }
#pragma unroll
            for (int i = 0; i < 4; i++)
#pragma unroll
                for (int t = 0; t < 4; t++)
                    mma_fp16(acc[i][t], af[i], bf[t]);
        }
        if (nxt) storeB(buf ^ 1, 1);
    }
    // epilogue -> out[b][oc][h][w] (+bias)
#pragma unroll
    for (int i = 0; i < 4; i++) {
        int oc0 = (warp_m * 4 + i) * 16 + (lane >> 2);
        float bv0 = bias[oc0], bv8 = bias[oc0 + 8];
#pragma unroll
        for (int t = 0; t < 4; t++) {
            int wcol = (warp_n * 4 + t) * 8 + (lane & 3) * 2;
            size_t base = ((size_t)(b * 256 + oc0)) * HW + h * 64 + wcol;
            *(float2*)&outp[base] = make_float2(acc[i][t][0] + bv0, acc[i][t][1] + bv0);
            *(float2*)&outp[base + 8 * HW] = make_float2(acc[i][t][2] + bv8, acc[i][t][3] + bv8);
        }
    }
}

// ---------------- launch ----------------------------------------------------
extern "C" void kernel_launch(void* const* d_in, const int* in_sizes, int n_in,
                              void* d_out, int out_size) {
    const float* x      = (const float*)d_in[0];
    const float* w_off  = (const float*)d_in[1];
    const float* b_off  = (const float*)d_in[2];
    const float* weight = (const float*)d_in[3];
    const float* bias   = (const float*)d_in[4];
    float* out = (float*)d_out;

    cudaFuncSetAttribute(k_maingemm, cudaFuncAttributeMaxDynamicSharedMemorySize, SMB_TOT);

    k_prep<<<1152 + 4096, 256>>>(weight, w_off, x);
    k_offgemm<<<256, 256>>>(b_off);
    k_maingemm<<<256, 256, SMB_TOT>>>(bias, out);
}